// round 1
// baseline (speedup 1.0000x reference)
#include <cuda_runtime.h>
#include <math.h>

#define B_ 4
#define N_ 4096
#define IN_DIM 256
#define OUT_DIM 128

// Scratch (no cudaMalloc allowed): h, and precomputed exp factors.
__device__ float  g_h[B_ * N_ * OUT_DIM];          // 8 MB
__device__ float2 g_S[B_ * N_];                    // (exp(s/2), exp(s/10)) per row i
__device__ float2 g_E[B_ * N_];                    // (exp(d/2), exp(d/10)) per col j

// ---------------------------------------------------------------------------
// k1: h = x @ W   (M=16384, K=256, N=128) — 128x128 block tile, 8x8 thread tile
// ---------------------------------------------------------------------------
__global__ void __launch_bounds__(256) k1_gemm(const float* __restrict__ x,
                                               const float* __restrict__ W) {
    __shared__ float xs[32][132];   // [k][m], padded to avoid STS conflicts
    __shared__ float ws[32][128];   // [k][n]
    const int tid = threadIdx.x;
    const int m0  = blockIdx.x * 128;
    const int tm  = (tid >> 4) << 3;   // 0..120
    const int tn  = (tid & 15) << 3;   // 0..120

    float acc[8][8];
#pragma unroll
    for (int i = 0; i < 8; i++)
#pragma unroll
        for (int j = 0; j < 8; j++) acc[i][j] = 0.f;

    for (int k0 = 0; k0 < IN_DIM; k0 += 32) {
        // x tile [128 rows x 32 k] -> transposed into xs[k][m]
#pragma unroll
        for (int i = 0; i < 4; i++) {
            int f   = tid + 256 * i;          // 0..1023 float4 slots
            int row = f >> 3;
            int kc  = (f & 7) << 2;
            float4 v = *(const float4*)&x[(size_t)(m0 + row) * IN_DIM + k0 + kc];
            xs[kc + 0][row] = v.x;
            xs[kc + 1][row] = v.y;
            xs[kc + 2][row] = v.z;
            xs[kc + 3][row] = v.w;
        }
        // W tile [32 x 128] direct copy
#pragma unroll
        for (int i = 0; i < 4; i++) {
            int f   = tid + 256 * i;          // 0..1023 float4 slots
            int row = f >> 5;
            int c   = (f & 31) << 2;
            *(float4*)&ws[row][c] = *(const float4*)&W[(size_t)(k0 + row) * OUT_DIM + c];
        }
        __syncthreads();
#pragma unroll
        for (int kk = 0; kk < 32; kk++) {
            float a[8], b[8];
            *(float4*)&a[0] = *(float4*)&xs[kk][tm];
            *(float4*)&a[4] = *(float4*)&xs[kk][tm + 4];
            *(float4*)&b[0] = *(float4*)&ws[kk][tn];
            *(float4*)&b[4] = *(float4*)&ws[kk][tn + 4];
#pragma unroll
            for (int i = 0; i < 8; i++)
#pragma unroll
                for (int j = 0; j < 8; j++) acc[i][j] += a[i] * b[j];
        }
        __syncthreads();
    }
#pragma unroll
    for (int i = 0; i < 8; i++) {
        float* hp = &g_h[(size_t)(m0 + tm + i) * OUT_DIM + tn];
        *(float4*)hp       = make_float4(acc[i][0], acc[i][1], acc[i][2], acc[i][3]);
        *(float4*)(hp + 4) = make_float4(acc[i][4], acc[i][5], acc[i][6], acc[i][7]);
    }
}

// ---------------------------------------------------------------------------
// k2: s = h.a_src, d = h.a_dst; store exp factors.
// w_ij = exp(leaky(s_i+d_j)/TAU) = max(exp((s+d)/2), exp(0.1(s+d)))
//      = max(S1_i*E1_j, S2_i*E2_j)
// ---------------------------------------------------------------------------
__global__ void __launch_bounds__(256) k2_sd(const float* __restrict__ a_src,
                                             const float* __restrict__ a_dst) {
    const int warp = threadIdx.x >> 5, lane = threadIdx.x & 31;
    const int row  = blockIdx.x * 8 + warp;   // 0..16383
    float4 hv = *(const float4*)&g_h[(size_t)row * OUT_DIM + lane * 4];
    float4 as = *(const float4*)&a_src[lane * 4];
    float4 ad = *(const float4*)&a_dst[lane * 4];
    float s = hv.x * as.x + hv.y * as.y + hv.z * as.z + hv.w * as.w;
    float d = hv.x * ad.x + hv.y * ad.y + hv.z * ad.z + hv.w * ad.w;
#pragma unroll
    for (int o = 16; o; o >>= 1) {
        s += __shfl_xor_sync(0xffffffffu, s, o);
        d += __shfl_xor_sync(0xffffffffu, d, o);
    }
    if (lane == 0) {
        g_S[row] = make_float2(expf(s * 0.5f), expf(s * 0.1f));
        g_E[row] = make_float2(expf(d * 0.5f), expf(d * 0.1f));
    }
}

// ---------------------------------------------------------------------------
// k3: fused masked-softmax + sparse aggregation.
// Block: 256 threads = 8 warps, 128 rows (16 rows/warp), lane owns 4 out dims.
// Loops j in tiles of 64 with h tile staged in shared memory.
// ---------------------------------------------------------------------------
__global__ void __launch_bounds__(256) k3_agg(const float* __restrict__ A,
                                              float* __restrict__ out) {
    __shared__ float hs[64][128];   // 32 KB h tile
    const int tid  = threadIdx.x;
    const int warp = tid >> 5, lane = tid & 31;
    const int b    = blockIdx.y;
    const int row0 = blockIdx.x * 128 + warp * 16;   // row within batch
    const size_t base = (size_t)b * N_;

    float  acc[16][4];
    float  z[16];
    float2 S[16];
#pragma unroll
    for (int r = 0; r < 16; r++) {
        acc[r][0] = acc[r][1] = acc[r][2] = acc[r][3] = 0.f;
        z[r] = 0.f;
        S[r] = g_S[base + row0 + r];
    }

    for (int jt = 0; jt < N_; jt += 64) {
        __syncthreads();
        // stage h[b][jt..jt+64][0..128] -> shared (2048 float4s, 8 per thread)
#pragma unroll
        for (int i = 0; i < 8; i++) {
            int f = tid + 256 * i;
            ((float4*)hs)[f] = *(const float4*)&g_h[(base + jt) * OUT_DIM + (size_t)f * 4];
        }
        __syncthreads();

        // per-j exp factors for this tile (lane covers j = jt+2*lane, +1)
        float4 ev = ((const float4*)(g_E + base + jt))[lane];
        const float E1a = ev.x, E2a = ev.y, E1b = ev.z, E2b = ev.w;

#pragma unroll
        for (int r = 0; r < 16; r++) {
            const float* Arow = A + (base + row0 + r) * (size_t)N_ + jt;
            float2 av = ((const float2*)Arow)[lane];
            float w0 = fmaxf(S[r].x * E1a, S[r].y * E2a);
            float w1 = fmaxf(S[r].x * E1b, S[r].y * E2b);
            bool m0 = av.x >= 1e-9f;
            bool m1 = av.y >= 1e-9f;
            z[r] += (m0 ? w0 : 0.f) + (m1 ? w1 : 0.f);
            unsigned bal0 = __ballot_sync(0xffffffffu, m0);
            unsigned bal1 = __ballot_sync(0xffffffffu, m1);
            while (bal0) {
                int src = __ffs(bal0) - 1;
                bal0 &= bal0 - 1;
                float w = __shfl_sync(0xffffffffu, w0, src);
                float4 hv = *(float4*)&hs[2 * src][lane * 4];
                acc[r][0] += w * hv.x; acc[r][1] += w * hv.y;
                acc[r][2] += w * hv.z; acc[r][3] += w * hv.w;
            }
            while (bal1) {
                int src = __ffs(bal1) - 1;
                bal1 &= bal1 - 1;
                float w = __shfl_sync(0xffffffffu, w1, src);
                float4 hv = *(float4*)&hs[2 * src + 1][lane * 4];
                acc[r][0] += w * hv.x; acc[r][1] += w * hv.y;
                acc[r][2] += w * hv.z; acc[r][3] += w * hv.w;
            }
        }
    }

    // normalize and write out (rows with no neighbors -> 0, matches nan_to_num)
#pragma unroll
    for (int r = 0; r < 16; r++) {
        float zz = z[r];
#pragma unroll
        for (int o = 16; o; o >>= 1) zz += __shfl_xor_sync(0xffffffffu, zz, o);
        float inv = zz > 0.f ? 1.f / zz : 0.f;
        float4 o4 = make_float4(acc[r][0] * inv, acc[r][1] * inv,
                                acc[r][2] * inv, acc[r][3] * inv);
        *(float4*)&out[(base + row0 + r) * OUT_DIM + (size_t)lane * 4] = o4;
    }
}

// ---------------------------------------------------------------------------
extern "C" void kernel_launch(void* const* d_in, const int* in_sizes, int n_in,
                              void* d_out, int out_size) {
    const float* x     = (const float*)d_in[0];   // [4,4096,256]
    const float* A     = (const float*)d_in[1];   // [4,4096,4096]
    const float* W     = (const float*)d_in[2];   // [256,128]
    const float* a_src = (const float*)d_in[3];   // [128]
    const float* a_dst = (const float*)d_in[4];   // [128]
    float* out = (float*)d_out;                   // [4,4096,128]

    k1_gemm<<<(B_ * N_) / 128, 256>>>(x, W);
    k2_sd<<<(B_ * N_) / 8, 256>>>(a_src, a_dst);
    dim3 g3(N_ / 128, B_);
    k3_agg<<<g3, 256>>>(A, out);
    (void)in_sizes; (void)n_in; (void)out_size;
}

// round 2
// speedup vs baseline: 3.9941x; 3.9941x over previous
#include <cuda_runtime.h>
#include <cuda_fp16.h>
#include <math.h>

#define B_ 4
#define N_ 4096
#define IN_DIM 256
#define OUT_DIM 128
#define NROWS (B_ * N_)
#define CAP 384   // max neighbors per row (binomial(4096,.05): mean 205, std 14)

// Scratch (no cudaMalloc allowed)
__device__ float  g_h [NROWS * OUT_DIM];   // 8 MB fp32 h (k2 input)
__device__ __half g_hh[NROWS * OUT_DIM];   // 4 MB fp16 h (kB gather)
__device__ float2 g_S [NROWS];             // (exp(s/2), exp(s/10))
__device__ float2 g_E [NROWS];             // (exp(d/2), exp(d/10))
__device__ int2   g_list[(size_t)NROWS * CAP];  // (h element offset, weight bits)
__device__ int    g_cnt[NROWS];
__device__ float  g_z  [NROWS];

// ---------------------------------------------------------------------------
// k1: h = x @ W  (M=16384, K=256, N=128); writes fp32 and fp16 copies
// ---------------------------------------------------------------------------
__global__ void __launch_bounds__(256) k1_gemm(const float* __restrict__ x,
                                               const float* __restrict__ W) {
    __shared__ float xs[32][132];
    __shared__ float ws[32][128];
    const int tid = threadIdx.x;
    const int m0  = blockIdx.x * 128;
    const int tm  = (tid >> 4) << 3;
    const int tn  = (tid & 15) << 3;

    float acc[8][8];
#pragma unroll
    for (int i = 0; i < 8; i++)
#pragma unroll
        for (int j = 0; j < 8; j++) acc[i][j] = 0.f;

    for (int k0 = 0; k0 < IN_DIM; k0 += 32) {
#pragma unroll
        for (int i = 0; i < 4; i++) {
            int f   = tid + 256 * i;
            int row = f >> 3;
            int kc  = (f & 7) << 2;
            float4 v = *(const float4*)&x[(size_t)(m0 + row) * IN_DIM + k0 + kc];
            xs[kc + 0][row] = v.x;
            xs[kc + 1][row] = v.y;
            xs[kc + 2][row] = v.z;
            xs[kc + 3][row] = v.w;
        }
#pragma unroll
        for (int i = 0; i < 4; i++) {
            int f   = tid + 256 * i;
            int row = f >> 5;
            int c   = (f & 31) << 2;
            *(float4*)&ws[row][c] = *(const float4*)&W[(size_t)(k0 + row) * OUT_DIM + c];
        }
        __syncthreads();
#pragma unroll
        for (int kk = 0; kk < 32; kk++) {
            float a[8], b[8];
            *(float4*)&a[0] = *(float4*)&xs[kk][tm];
            *(float4*)&a[4] = *(float4*)&xs[kk][tm + 4];
            *(float4*)&b[0] = *(float4*)&ws[kk][tn];
            *(float4*)&b[4] = *(float4*)&ws[kk][tn + 4];
#pragma unroll
            for (int i = 0; i < 8; i++)
#pragma unroll
                for (int j = 0; j < 8; j++) acc[i][j] += a[i] * b[j];
        }
        __syncthreads();
    }
#pragma unroll
    for (int i = 0; i < 8; i++) {
        size_t ro = (size_t)(m0 + tm + i) * OUT_DIM + tn;
        *(float4*)&g_h[ro]     = make_float4(acc[i][0], acc[i][1], acc[i][2], acc[i][3]);
        *(float4*)&g_h[ro + 4] = make_float4(acc[i][4], acc[i][5], acc[i][6], acc[i][7]);
        __half2 p0 = __floats2half2_rn(acc[i][0], acc[i][1]);
        __half2 p1 = __floats2half2_rn(acc[i][2], acc[i][3]);
        __half2 p2 = __floats2half2_rn(acc[i][4], acc[i][5]);
        __half2 p3 = __floats2half2_rn(acc[i][6], acc[i][7]);
        uint4 u;
        u.x = *(unsigned*)&p0; u.y = *(unsigned*)&p1;
        u.z = *(unsigned*)&p2; u.w = *(unsigned*)&p3;
        *(uint4*)&g_hh[ro] = u;
    }
}

// ---------------------------------------------------------------------------
// k2: s = h.a_src, d = h.a_dst; exp factor tables.
// exp(leaky(s+d)/2) = max(exp((s+d)/2), exp((s+d)/10)) = max(S1*E1, S2*E2)
// ---------------------------------------------------------------------------
__global__ void __launch_bounds__(256) k2_sd(const float* __restrict__ a_src,
                                             const float* __restrict__ a_dst) {
    const int warp = threadIdx.x >> 5, lane = threadIdx.x & 31;
    const int row  = blockIdx.x * 8 + warp;
    float4 hv = *(const float4*)&g_h[(size_t)row * OUT_DIM + lane * 4];
    float4 as = *(const float4*)&a_src[lane * 4];
    float4 ad = *(const float4*)&a_dst[lane * 4];
    float s = hv.x * as.x + hv.y * as.y + hv.z * as.z + hv.w * as.w;
    float d = hv.x * ad.x + hv.y * ad.y + hv.z * ad.z + hv.w * ad.w;
#pragma unroll
    for (int o = 16; o; o >>= 1) {
        s += __shfl_xor_sync(0xffffffffu, s, o);
        d += __shfl_xor_sync(0xffffffffu, d, o);
    }
    if (lane == 0) {
        g_S[row] = make_float2(expf(s * 0.5f), expf(s * 0.1f));
        g_E[row] = make_float2(expf(d * 0.5f), expf(d * 0.1f));
    }
}

// ---------------------------------------------------------------------------
// kA: stream A, compact nonzero (offset, weight) lists per row + z sums.
// One warp per row; ballot+popc compaction, branch-free weight compute.
// ---------------------------------------------------------------------------
__global__ void __launch_bounds__(256) kA_build(const float* __restrict__ A) {
    const int gwarp = (blockIdx.x * 256 + threadIdx.x) >> 5;
    const int lane  = threadIdx.x & 31;
    const int row   = gwarp;                 // 0..16383
    const int base  = row & ~(N_ - 1);       // batch row offset (b*4096)
    const unsigned lmlt = (1u << lane) - 1u;

    const float* Arow = A + (size_t)row * N_;
    const float2 Sv = g_S[row];
    int2* lst = g_list + (size_t)row * CAP;

    int   cnt  = 0;
    float zacc = 0.f;

    for (int c0 = 0; c0 < N_; c0 += 128) {
        const int j0 = c0 + lane * 4;
        float4 av = *(const float4*)&Arow[j0];
        float4 Ea = *(const float4*)&g_E[base + j0];       // e[j0], e[j0+1]
        float4 Eb = *(const float4*)&g_E[base + j0 + 2];   // e[j0+2], e[j0+3]

        float w0 = fmaxf(Sv.x * Ea.x, Sv.y * Ea.y);
        float w1 = fmaxf(Sv.x * Ea.z, Sv.y * Ea.w);
        float w2 = fmaxf(Sv.x * Eb.x, Sv.y * Eb.y);
        float w3 = fmaxf(Sv.x * Eb.z, Sv.y * Eb.w);

        bool m0 = av.x >= 1e-9f, m1 = av.y >= 1e-9f;
        bool m2 = av.z >= 1e-9f, m3 = av.w >= 1e-9f;

        unsigned b0 = __ballot_sync(0xffffffffu, m0);
        unsigned b1 = __ballot_sync(0xffffffffu, m1);
        unsigned b2 = __ballot_sync(0xffffffffu, m2);
        unsigned b3 = __ballot_sync(0xffffffffu, m3);

        if (m0) { int p = cnt + __popc(b0 & lmlt);
                  if (p < CAP) lst[p] = make_int2((base + j0) << 7, __float_as_int(w0));
                  zacc += w0; }
        cnt += __popc(b0);
        if (m1) { int p = cnt + __popc(b1 & lmlt);
                  if (p < CAP) lst[p] = make_int2((base + j0 + 1) << 7, __float_as_int(w1));
                  zacc += w1; }
        cnt += __popc(b1);
        if (m2) { int p = cnt + __popc(b2 & lmlt);
                  if (p < CAP) lst[p] = make_int2((base + j0 + 2) << 7, __float_as_int(w2));
                  zacc += w2; }
        cnt += __popc(b2);
        if (m3) { int p = cnt + __popc(b3 & lmlt);
                  if (p < CAP) lst[p] = make_int2((base + j0 + 3) << 7, __float_as_int(w3));
                  zacc += w3; }
        cnt += __popc(b3);
    }

#pragma unroll
    for (int o = 16; o; o >>= 1) zacc += __shfl_xor_sync(0xffffffffu, zacc, o);
    if (lane == 0) {
        g_cnt[row] = cnt < CAP ? cnt : CAP;
        g_z[row]   = zacc;
    }
}

// ---------------------------------------------------------------------------
// kB: sparse gather-aggregate. Warp per row; uniform list loads + coalesced
// fp16 h gathers, unrolled x8 for MLP. Branch-free inner body.
// ---------------------------------------------------------------------------
__global__ void __launch_bounds__(256) kB_agg(float* __restrict__ out) {
    const int gwarp = (blockIdx.x * 256 + threadIdx.x) >> 5;
    const int lane  = threadIdx.x & 31;
    const int row   = gwarp;

    const int   cnt = g_cnt[row];
    const float z   = g_z[row];
    const int2* lst = g_list + (size_t)row * CAP;

    float ax = 0.f, ay = 0.f, az = 0.f, aw = 0.f;
    const int loff = lane * 4;

    int k = 0;
    for (; k + 8 <= cnt; k += 8) {
        int2 e[8];
#pragma unroll
        for (int u = 0; u < 8; u++) e[u] = lst[k + u];
#pragma unroll
        for (int u = 0; u < 8; u++) {
            uint2 raw = *(const uint2*)(g_hh + (size_t)e[u].x + loff);
            __half2 h01 = *(__half2*)&raw.x;
            __half2 h23 = *(__half2*)&raw.y;
            float2 f01 = __half22float2(h01);
            float2 f23 = __half22float2(h23);
            float w = __int_as_float(e[u].y);
            ax += w * f01.x; ay += w * f01.y;
            az += w * f23.x; aw += w * f23.y;
        }
    }
    for (; k < cnt; k++) {
        int2 e = lst[k];
        uint2 raw = *(const uint2*)(g_hh + (size_t)e.x + loff);
        __half2 h01 = *(__half2*)&raw.x;
        __half2 h23 = *(__half2*)&raw.y;
        float2 f01 = __half22float2(h01);
        float2 f23 = __half22float2(h23);
        float w = __int_as_float(e.y);
        ax += w * f01.x; ay += w * f01.y;
        az += w * f23.x; aw += w * f23.y;
    }

    float inv = z > 0.f ? 1.f / z : 0.f;
    *(float4*)&out[(size_t)row * OUT_DIM + loff] =
        make_float4(ax * inv, ay * inv, az * inv, aw * inv);
}

// ---------------------------------------------------------------------------
extern "C" void kernel_launch(void* const* d_in, const int* in_sizes, int n_in,
                              void* d_out, int out_size) {
    const float* x     = (const float*)d_in[0];   // [4,4096,256]
    const float* A     = (const float*)d_in[1];   // [4,4096,4096]
    const float* W     = (const float*)d_in[2];   // [256,128]
    const float* a_src = (const float*)d_in[3];   // [128]
    const float* a_dst = (const float*)d_in[4];   // [128]
    float* out = (float*)d_out;                   // [4,4096,128]

    k1_gemm<<<NROWS / 128, 256>>>(x, W);
    k2_sd  <<<NROWS / 8,   256>>>(a_src, a_dst);
    kA_build<<<NROWS / 8,  256>>>(A);
    kB_agg <<<NROWS / 8,   256>>>(out);
    (void)in_sizes; (void)n_in; (void)out_size;
}

// round 4
// speedup vs baseline: 4.9056x; 1.2282x over previous
#include <cuda_runtime.h>
#include <cuda_fp16.h>
#include <math.h>
#include <stdint.h>

#define B_ 4
#define N_ 4096
#define IN_DIM 256
#define OUT_DIM 128
#define NROWS (B_ * N_)
#define TJ 64              // j-tile (K of the aggregation MMA)
#define NT (N_ / TJ)       // 64 tiles
#define PADH 72            // smem row pitch in halves (64 data + 8 pad -> 144B)

// Scratch (no cudaMalloc allowed)
__device__ float  g_h [NROWS * OUT_DIM];          // fp32 h (k2 input)
__device__ __half g_hT[(size_t)B_ * OUT_DIM * N_];// f16 h transposed: [b][d][j]
__device__ float2 g_S [NROWS];                    // (exp(s/2), exp(s/10))
__device__ float2 g_E [NROWS];                    // (exp(d/2), exp(d/10))

// ---------------------------------------------------------------------------
__device__ __forceinline__ uint32_t sm_u32(const void* p) {
    uint32_t a;
    asm("{ .reg .u64 t; cvta.to.shared.u64 t, %1; cvt.u32.u64 %0, t; }"
        : "=r"(a) : "l"(p));
    return a;
}
__device__ __forceinline__ void ldsm_x4(uint32_t& r0, uint32_t& r1,
                                        uint32_t& r2, uint32_t& r3,
                                        uint32_t addr) {
    asm volatile("ldmatrix.sync.aligned.m8n8.x4.shared.b16 {%0,%1,%2,%3}, [%4];"
                 : "=r"(r0), "=r"(r1), "=r"(r2), "=r"(r3) : "r"(addr));
}
__device__ __forceinline__ void mma16816(float* c,
                                         uint32_t a0, uint32_t a1,
                                         uint32_t a2, uint32_t a3,
                                         uint32_t b0, uint32_t b1) {
    asm volatile("mma.sync.aligned.m16n8k16.row.col.f32.f16.f16.f32 "
                 "{%0,%1,%2,%3},{%4,%5,%6,%7},{%8,%9},{%0,%1,%2,%3};"
                 : "+f"(c[0]), "+f"(c[1]), "+f"(c[2]), "+f"(c[3])
                 : "r"(a0), "r"(a1), "r"(a2), "r"(a3), "r"(b0), "r"(b1));
}

// ---------------------------------------------------------------------------
// k1: h = x @ W; writes fp32 h and f16 h^T ([b][d][j])
// ---------------------------------------------------------------------------
__global__ void __launch_bounds__(256) k1_gemm(const float* __restrict__ x,
                                               const float* __restrict__ W) {
    __shared__ float xs[32][132];
    __shared__ float ws[32][128];
    const int tid = threadIdx.x;
    const int m0  = blockIdx.x * 128;
    const int tm  = (tid >> 4) << 3;
    const int tn  = (tid & 15) << 3;

    float acc[8][8];
#pragma unroll
    for (int i = 0; i < 8; i++)
#pragma unroll
        for (int j = 0; j < 8; j++) acc[i][j] = 0.f;

    for (int k0 = 0; k0 < IN_DIM; k0 += 32) {
#pragma unroll
        for (int i = 0; i < 4; i++) {
            int f   = tid + 256 * i;
            int row = f >> 3;
            int kc  = (f & 7) << 2;
            float4 v = *(const float4*)&x[(size_t)(m0 + row) * IN_DIM + k0 + kc];
            xs[kc + 0][row] = v.x;
            xs[kc + 1][row] = v.y;
            xs[kc + 2][row] = v.z;
            xs[kc + 3][row] = v.w;
        }
#pragma unroll
        for (int i = 0; i < 4; i++) {
            int f   = tid + 256 * i;
            int row = f >> 5;
            int c   = (f & 31) << 2;
            *(float4*)&ws[row][c] = *(const float4*)&W[(size_t)(k0 + row) * OUT_DIM + c];
        }
        __syncthreads();
#pragma unroll
        for (int kk = 0; kk < 32; kk++) {
            float a[8], b[8];
            *(float4*)&a[0] = *(float4*)&xs[kk][tm];
            *(float4*)&a[4] = *(float4*)&xs[kk][tm + 4];
            *(float4*)&b[0] = *(float4*)&ws[kk][tn];
            *(float4*)&b[4] = *(float4*)&ws[kk][tn + 4];
#pragma unroll
            for (int i = 0; i < 8; i++)
#pragma unroll
                for (int j = 0; j < 8; j++) acc[i][j] += a[i] * b[j];
        }
        __syncthreads();
    }
#pragma unroll
    for (int i = 0; i < 8; i++) {
        size_t ro = (size_t)(m0 + tm + i) * OUT_DIM + tn;
        *(float4*)&g_h[ro]     = make_float4(acc[i][0], acc[i][1], acc[i][2], acc[i][3]);
        *(float4*)&g_h[ro + 4] = make_float4(acc[i][4], acc[i][5], acc[i][6], acc[i][7]);
    }
    // h^T f16: for each dim j, pack 8 consecutive rows
    const int b    = m0 >> 12;
    const int mloc = (m0 & (N_ - 1)) + tm;
#pragma unroll
    for (int j = 0; j < 8; j++) {
        __half2 q0 = __floats2half2_rn(acc[0][j], acc[1][j]);
        __half2 q1 = __floats2half2_rn(acc[2][j], acc[3][j]);
        __half2 q2 = __floats2half2_rn(acc[4][j], acc[5][j]);
        __half2 q3 = __floats2half2_rn(acc[6][j], acc[7][j]);
        uint4 u;
        u.x = *(uint32_t*)&q0; u.y = *(uint32_t*)&q1;
        u.z = *(uint32_t*)&q2; u.w = *(uint32_t*)&q3;
        *(uint4*)&g_hT[((size_t)(b * OUT_DIM + tn + j)) * N_ + mloc] = u;
    }
}

// ---------------------------------------------------------------------------
// k2: s = h.a_src, d = h.a_dst; exp factor tables.
// exp(leaky(t)/2) = max(exp(t/2), exp(t/10)) = max(S1*E1, S2*E2)
// ---------------------------------------------------------------------------
__global__ void __launch_bounds__(256) k2_sd(const float* __restrict__ a_src,
                                             const float* __restrict__ a_dst) {
    const int warp = threadIdx.x >> 5, lane = threadIdx.x & 31;
    const int row  = blockIdx.x * 8 + warp;
    float4 hv = *(const float4*)&g_h[(size_t)row * OUT_DIM + lane * 4];
    float4 as = *(const float4*)&a_src[lane * 4];
    float4 ad = *(const float4*)&a_dst[lane * 4];
    float s = hv.x * as.x + hv.y * as.y + hv.z * as.z + hv.w * as.w;
    float d = hv.x * ad.x + hv.y * ad.y + hv.z * ad.z + hv.w * ad.w;
#pragma unroll
    for (int o = 16; o; o >>= 1) {
        s += __shfl_xor_sync(0xffffffffu, s, o);
        d += __shfl_xor_sync(0xffffffffu, d, o);
    }
    if (lane == 0) {
        g_S[row] = make_float2(expf(s * 0.5f), expf(s * 0.1f));
        g_E[row] = make_float2(expf(d * 0.5f), expf(d * 0.1f));
    }
}

// ---------------------------------------------------------------------------
// kAB: fused masked-softmax weight compute + mma.sync f16 aggregation.
// Grid 128 CTAs x 256 thr. CTA: 128 rows; K-loop over 64-wide j tiles.
// Single-buffer SMEM; register prefetch overlaps next tile's DRAM loads
// with current tile's HMMA.
// ---------------------------------------------------------------------------
__global__ void __launch_bounds__(256) kAB(const float* __restrict__ A,
                                           float* __restrict__ out) {
    __shared__ __half sh_a[128 * PADH];   // alpha tile [m=128][k=64] padded
    __shared__ __half sh_h[128 * PADH];   // hT tile    [n=128][k=64] padded
    __shared__ float  s_z[128];

    const int tid  = threadIdx.x;
    const int wid  = tid >> 5, lane = tid & 31;
    const int batch = blockIdx.x >> 5;
    const int row0  = (blockIdx.x & 31) << 7;
    const size_t rbase = (size_t)batch * N_;

    const uint32_t a_base = sm_u32(sh_a);
    const uint32_t h_base = sm_u32(sh_h);

    // per-warp row params
    float S1[16], S2[16], z[16];
#pragma unroll
    for (int r = 0; r < 16; r++) {
        float2 sv = g_S[rbase + row0 + wid * 16 + r];
        S1[r] = sv.x; S2[r] = sv.y; z[r] = 0.f;
    }

    const float*  Abase = A + (rbase + row0 + wid * 16) * (size_t)N_ + 2 * lane;
    const __half* hTb   = g_hT + (size_t)batch * OUT_DIM * N_;

    // accumulators: 16 n-tiles x 4 (m16n8 C fragment)
    float c[16][4];
#pragma unroll
    for (int p = 0; p < 16; p++)
        c[p][0] = c[p][1] = c[p][2] = c[p][3] = 0.f;

    // prefetch regs
    float2 Ar[16];
    uint4  Hr[4];
    float4 Ev;

    // ldmatrix address bases (per-lane constants)
    const uint32_t aaddr0 = a_base + (wid * 16 + (lane & 15)) * (PADH * 2)
                          + ((lane >> 4) << 4);
    const uint32_t baddr0 = h_base + (((lane >> 4) << 3) + (lane & 7)) * (PADH * 2)
                          + (((lane >> 3) & 1) << 4);

#define PREFETCH(JT)                                                          \
    do {                                                                      \
        Ev = *(const float4*)(g_E + rbase + (JT) + 2 * lane);                 \
        _Pragma("unroll")                                                     \
        for (int r = 0; r < 16; r++)                                          \
            Ar[r] = *(const float2*)(Abase + (size_t)r * N_ + (JT));          \
        _Pragma("unroll")                                                     \
        for (int i = 0; i < 4; i++) {                                         \
            int f = i * 256 + tid;                                            \
            int dd = f >> 3, cc = f & 7;                                      \
            Hr[i] = *(const uint4*)(hTb + (size_t)dd * N_ + (JT) + cc * 8);   \
        }                                                                     \
    } while (0)

#define STORE_TILE()                                                          \
    do {                                                                      \
        _Pragma("unroll")                                                     \
        for (int r = 0; r < 16; r++) {                                        \
            float w0 = fmaxf(S1[r] * Ev.x, S2[r] * Ev.y);                     \
            float w1 = fmaxf(S1[r] * Ev.z, S2[r] * Ev.w);                     \
            w0 = Ar[r].x >= 1e-9f ? w0 : 0.f;                                 \
            w1 = Ar[r].y >= 1e-9f ? w1 : 0.f;                                 \
            z[r] += w0 + w1;                                                  \
            __half2 pk = __floats2half2_rn(w0, w1);                           \
            *(__half2*)&sh_a[(wid * 16 + r) * PADH + 2 * lane] = pk;          \
        }                                                                     \
        _Pragma("unroll")                                                     \
        for (int i = 0; i < 4; i++) {                                         \
            int f = i * 256 + tid;                                            \
            int dd = f >> 3, cc = f & 7;                                      \
            *(uint4*)&sh_h[dd * PADH + cc * 8] = Hr[i];                       \
        }                                                                     \
    } while (0)

    PREFETCH(0);
    STORE_TILE();
    __syncthreads();

    for (int t = 0; t < NT; t++) {
        if (t + 1 < NT) PREFETCH((t + 1) * TJ);

        // HMMA over the staged tile: K=64 (4 k-steps), N=128 (16 n-tiles)
#pragma unroll
        for (int ks = 0; ks < 4; ks++) {
            uint32_t a0, a1, a2, a3;
            ldsm_x4(a0, a1, a2, a3, aaddr0 + ks * 32);
#pragma unroll
            for (int p = 0; p < 8; p++) {
                uint32_t b0, b1, b2, b3;
                ldsm_x4(b0, b1, b2, b3, baddr0 + p * (16 * PADH * 2) + ks * 32);
                mma16816(c[2 * p],     a0, a1, a2, a3, b0, b1);
                mma16816(c[2 * p + 1], a0, a1, a2, a3, b2, b3);
            }
        }
        __syncthreads();
        if (t + 1 < NT) {
            STORE_TILE();
            __syncthreads();
        }
    }

    // z row sums -> smem
#pragma unroll
    for (int r = 0; r < 16; r++) {
        float zz = z[r];
#pragma unroll
        for (int o = 16; o; o >>= 1) zz += __shfl_xor_sync(0xffffffffu, zz, o);
        if (lane == 0) s_z[wid * 16 + r] = zz;
    }
    __syncthreads();

    // epilogue: scale by 1/z and store
    const int mlo = wid * 16 + (lane >> 2);
    const float zlo = s_z[mlo], zhi = s_z[mlo + 8];
    const float invlo = zlo > 0.f ? 1.f / zlo : 0.f;
    const float invhi = zhi > 0.f ? 1.f / zhi : 0.f;
    float* olo = out + (rbase + row0 + mlo) * OUT_DIM + 2 * (lane & 3);
    float* ohi = olo + 8 * OUT_DIM;
#pragma unroll
    for (int p = 0; p < 16; p++) {
        *(float2*)(olo + p * 8) = make_float2(c[p][0] * invlo, c[p][1] * invlo);
        *(float2*)(ohi + p * 8) = make_float2(c[p][2] * invhi, c[p][3] * invhi);
    }
}

// ---------------------------------------------------------------------------
extern "C" void kernel_launch(void* const* d_in, const int* in_sizes, int n_in,
                              void* d_out, int out_size) {
    const float* x     = (const float*)d_in[0];   // [4,4096,256]
    const float* A     = (const float*)d_in[1];   // [4,4096,4096]
    const float* W     = (const float*)d_in[2];   // [256,128]
    const float* a_src = (const float*)d_in[3];   // [128]
    const float* a_dst = (const float*)d_in[4];   // [128]
    float* out = (float*)d_out;                   // [4,4096,128]

    k1_gemm<<<NROWS / 128, 256>>>(x, W);
    k2_sd  <<<NROWS / 8,   256>>>(a_src, a_dst);
    kAB    <<<NROWS / 128, 256>>>(A, out);
    (void)in_sizes; (void)n_in; (void)out_size;
}

// round 5
// speedup vs baseline: 5.0341x; 1.0262x over previous
#include <cuda_runtime.h>
#include <cuda_fp16.h>
#include <math.h>
#include <stdint.h>

#define B_ 4
#define N_ 4096
#define IN_DIM 256
#define OUT_DIM 128
#define NROWS (B_ * N_)
#define TJ 64              // j-tile (K of the aggregation MMA)
#define NT (N_ / TJ)       // 64 tiles
#define PADH 72            // smem row pitch in halves (64 data + 8 pad -> 144B)
#define RCTA 64            // rows per kAB CTA

// Scratch (no cudaMalloc allowed)
__device__ float  g_h [NROWS * OUT_DIM];          // fp32 h (k2 input)
__device__ __half g_hT[(size_t)B_ * OUT_DIM * N_];// f16 h transposed: [b][d][j]
__device__ float2 g_S [NROWS];                    // (exp(s/2), exp(s/10))
__device__ float2 g_E [NROWS];                    // (exp(d/2), exp(d/10))

// ---------------------------------------------------------------------------
__device__ __forceinline__ uint32_t sm_u32(const void* p) {
    uint32_t a;
    asm("{ .reg .u64 t; cvta.to.shared.u64 t, %1; cvt.u32.u64 %0, t; }"
        : "=r"(a) : "l"(p));
    return a;
}
__device__ __forceinline__ void ldsm_x4(uint32_t& r0, uint32_t& r1,
                                        uint32_t& r2, uint32_t& r3,
                                        uint32_t addr) {
    asm volatile("ldmatrix.sync.aligned.m8n8.x4.shared.b16 {%0,%1,%2,%3}, [%4];"
                 : "=r"(r0), "=r"(r1), "=r"(r2), "=r"(r3) : "r"(addr));
}
__device__ __forceinline__ void mma16816(float* c,
                                         uint32_t a0, uint32_t a1,
                                         uint32_t a2, uint32_t a3,
                                         uint32_t b0, uint32_t b1) {
    asm volatile("mma.sync.aligned.m16n8k16.row.col.f32.f16.f16.f32 "
                 "{%0,%1,%2,%3},{%4,%5,%6,%7},{%8,%9},{%0,%1,%2,%3};"
                 : "+f"(c[0]), "+f"(c[1]), "+f"(c[2]), "+f"(c[3])
                 : "r"(a0), "r"(a1), "r"(a2), "r"(a3), "r"(b0), "r"(b1));
}

// ---------------------------------------------------------------------------
// k1: h = x @ W  (64-row blocks, grid 256, 4x8 thread tile, conflict-free B)
// Writes fp32 h and f16 h^T ([b][d][j]).
// ---------------------------------------------------------------------------
__global__ void __launch_bounds__(256) k1_gemm(const float* __restrict__ x,
                                               const float* __restrict__ W) {
    __shared__ float xs[32][68];    // [k][m] transposed
    __shared__ float ws[32][128];   // [k][n]
    const int tid = threadIdx.x;
    const int m0  = blockIdx.x * 64;
    const int tm  = (tid >> 4) << 2;   // 0..60 (4 rows)
    const int tn  = (tid & 15) << 2;   // 0..60 (cols tn..tn+3, tn+64..tn+67)

    float acc[4][8];
#pragma unroll
    for (int i = 0; i < 4; i++)
#pragma unroll
        for (int j = 0; j < 8; j++) acc[i][j] = 0.f;

    for (int k0 = 0; k0 < IN_DIM; k0 += 32) {
#pragma unroll
        for (int i = 0; i < 2; i++) {
            int f   = tid + 256 * i;      // 0..511 float4 slots (64x32)
            int row = f >> 3;
            int kc  = (f & 7) << 2;
            float4 v = *(const float4*)&x[(size_t)(m0 + row) * IN_DIM + k0 + kc];
            xs[kc + 0][row] = v.x;
            xs[kc + 1][row] = v.y;
            xs[kc + 2][row] = v.z;
            xs[kc + 3][row] = v.w;
        }
#pragma unroll
        for (int i = 0; i < 4; i++) {
            int f   = tid + 256 * i;      // 0..1023 float4 slots (32x128)
            int row = f >> 5;
            int c   = (f & 31) << 2;
            *(float4*)&ws[row][c] = *(const float4*)&W[(size_t)(k0 + row) * OUT_DIM + c];
        }
        __syncthreads();
#pragma unroll
        for (int kk = 0; kk < 32; kk++) {
            float4 a  = *(float4*)&xs[kk][tm];
            float4 b0 = *(float4*)&ws[kk][tn];
            float4 b1 = *(float4*)&ws[kk][tn + 64];
            float av[4] = {a.x, a.y, a.z, a.w};
            float bv[8] = {b0.x, b0.y, b0.z, b0.w, b1.x, b1.y, b1.z, b1.w};
#pragma unroll
            for (int i = 0; i < 4; i++)
#pragma unroll
                for (int j = 0; j < 8; j++) acc[i][j] += av[i] * bv[j];
        }
        __syncthreads();
    }
#pragma unroll
    for (int i = 0; i < 4; i++) {
        size_t ro = (size_t)(m0 + tm + i) * OUT_DIM;
        *(float4*)&g_h[ro + tn]      = make_float4(acc[i][0], acc[i][1], acc[i][2], acc[i][3]);
        *(float4*)&g_h[ro + tn + 64] = make_float4(acc[i][4], acc[i][5], acc[i][6], acc[i][7]);
    }
    // h^T f16: thread's 4 consecutive rows packed per column
    const int b    = m0 >> 12;
    const int mloc = (m0 & (N_ - 1)) + tm;
#pragma unroll
    for (int j = 0; j < 8; j++) {
        int col = (j < 4) ? (tn + j) : (tn + 60 + j);
        __half2 q0 = __floats2half2_rn(acc[0][j], acc[1][j]);
        __half2 q1 = __floats2half2_rn(acc[2][j], acc[3][j]);
        uint2 u;
        u.x = *(uint32_t*)&q0; u.y = *(uint32_t*)&q1;
        *(uint2*)&g_hT[((size_t)(b * OUT_DIM + col)) * N_ + mloc] = u;
    }
}

// ---------------------------------------------------------------------------
// k2: s = h.a_src, d = h.a_dst; exp factor tables.
// exp(leaky(t)/2) = max(exp(t/2), exp(t/10)) = max(S1*E1, S2*E2)
// ---------------------------------------------------------------------------
__global__ void __launch_bounds__(256) k2_sd(const float* __restrict__ a_src,
                                             const float* __restrict__ a_dst) {
    const int warp = threadIdx.x >> 5, lane = threadIdx.x & 31;
    const int row  = blockIdx.x * 8 + warp;
    float4 hv = *(const float4*)&g_h[(size_t)row * OUT_DIM + lane * 4];
    float4 as = *(const float4*)&a_src[lane * 4];
    float4 ad = *(const float4*)&a_dst[lane * 4];
    float s = hv.x * as.x + hv.y * as.y + hv.z * as.z + hv.w * as.w;
    float d = hv.x * ad.x + hv.y * ad.y + hv.z * ad.z + hv.w * ad.w;
#pragma unroll
    for (int o = 16; o; o >>= 1) {
        s += __shfl_xor_sync(0xffffffffu, s, o);
        d += __shfl_xor_sync(0xffffffffu, d, o);
    }
    if (lane == 0) {
        g_S[row] = make_float2(expf(s * 0.5f), expf(s * 0.1f));
        g_E[row] = make_float2(expf(d * 0.5f), expf(d * 0.1f));
    }
}

// ---------------------------------------------------------------------------
// kAB: fused masked-softmax weights + mma.sync f16 aggregation.
// Grid 256 CTAs (64 rows each), 2 CTAs/SM, double-buffered SMEM,
// one __syncthreads per tile. Warps 0-3: n-cols 0-63; warps 4-7: 64-127.
// ---------------------------------------------------------------------------
#define A_TILE_B  (RCTA * PADH * 2)        // 9216
#define H_TILE_B  (OUT_DIM * PADH * 2)     // 18432
#define DSM_BYTES (2 * A_TILE_B + 2 * H_TILE_B)  // 55296

__global__ void __launch_bounds__(256, 2) kAB(const float* __restrict__ A,
                                              float* __restrict__ out) {
    extern __shared__ __align__(16) char dsm[];
    __shared__ float s_z[RCTA];

    const int tid  = threadIdx.x;
    const int wid  = tid >> 5, lane = tid & 31;
    const int batch = blockIdx.x >> 6;
    const int row0  = (blockIdx.x & 63) << 6;
    const size_t rbase = (size_t)batch * N_;

    const uint32_t smb = sm_u32(dsm);
    const uint32_t a_off[2] = {0u, (uint32_t)A_TILE_B};
    const uint32_t h_off[2] = {(uint32_t)(2 * A_TILE_B),
                               (uint32_t)(2 * A_TILE_B + H_TILE_B)};

    // weight-compute rows: wid*8 .. wid*8+7
    float S1[8], S2[8], z[8];
#pragma unroll
    for (int r = 0; r < 8; r++) {
        float2 sv = g_S[rbase + row0 + wid * 8 + r];
        S1[r] = sv.x; S2[r] = sv.y; z[r] = 0.f;
    }
    const float*  Abase = A + (rbase + row0 + wid * 8) * (size_t)N_ + 2 * lane;
    const __half* hTb   = g_hT + (size_t)batch * OUT_DIM * N_;

    // mma assignment: mtile = wid&3 (rows 16*mtile..+15), nh = wid>>2 (col half)
    const int mtile = wid & 3, nh = wid >> 2;
    const uint32_t aaddr_l = (uint32_t)((mtile * 16 + (lane & 15)) * (PADH * 2)
                                        + ((lane >> 4) << 4));
    const uint32_t baddr_l = (uint32_t)((nh * 64 + ((lane >> 4) << 3) + (lane & 7)) * (PADH * 2)
                                        + (((lane >> 3) & 1) << 4));

    float c[8][4];
#pragma unroll
    for (int q = 0; q < 8; q++)
        c[q][0] = c[q][1] = c[q][2] = c[q][3] = 0.f;

    float2 Ar[8];
    uint4  Hr[4];
    float4 Ev;

#define PREFETCH(JT)                                                          \
    do {                                                                      \
        Ev = *(const float4*)(g_E + rbase + (JT) + 2 * lane);                 \
        _Pragma("unroll")                                                     \
        for (int r = 0; r < 8; r++)                                           \
            Ar[r] = *(const float2*)(Abase + (size_t)r * N_ + (JT));          \
        _Pragma("unroll")                                                     \
        for (int i = 0; i < 4; i++) {                                         \
            int f = i * 256 + tid;                                            \
            int dd = f >> 3, cc = f & 7;                                      \
            Hr[i] = *(const uint4*)(hTb + (size_t)dd * N_ + (JT) + cc * 8);   \
        }                                                                     \
    } while (0)

#define STORE_TILE(BUF)                                                       \
    do {                                                                      \
        __half* sa = (__half*)(dsm + a_off[BUF]);                             \
        _Pragma("unroll")                                                     \
        for (int r = 0; r < 8; r++) {                                         \
            float w0 = fmaxf(S1[r] * Ev.x, S2[r] * Ev.y);                     \
            float w1 = fmaxf(S1[r] * Ev.z, S2[r] * Ev.w);                     \
            w0 = Ar[r].x >= 1e-9f ? w0 : 0.f;                                 \
            w1 = Ar[r].y >= 1e-9f ? w1 : 0.f;                                 \
            z[r] += w0 + w1;                                                  \
            __half2 pk = __floats2half2_rn(w0, w1);                           \
            *(__half2*)&sa[(wid * 8 + r) * PADH + 2 * lane] = pk;             \
        }                                                                     \
        __half* shh = (__half*)(dsm + h_off[BUF]);                            \
        _Pragma("unroll")                                                     \
        for (int i = 0; i < 4; i++) {                                         \
            int f = i * 256 + tid;                                            \
            int dd = f >> 3, cc = f & 7;                                      \
            *(uint4*)&shh[dd * PADH + cc * 8] = Hr[i];                        \
        }                                                                     \
    } while (0)

    PREFETCH(0);
    STORE_TILE(0);
    __syncthreads();

    for (int t = 0; t < NT; t++) {
        if (t + 1 < NT) PREFETCH((t + 1) * TJ);

        const int buf = t & 1;
        const uint32_t abase = smb + a_off[buf] + aaddr_l;
        const uint32_t bbase = smb + h_off[buf] + baddr_l;
#pragma unroll
        for (int ks = 0; ks < 4; ks++) {
            uint32_t a0, a1, a2, a3;
            ldsm_x4(a0, a1, a2, a3, abase + ks * 32);
#pragma unroll
            for (int p = 0; p < 4; p++) {
                uint32_t b0, b1, b2, b3;
                ldsm_x4(b0, b1, b2, b3, bbase + p * (16 * PADH * 2) + ks * 32);
                mma16816(c[2 * p],     a0, a1, a2, a3, b0, b1);
                mma16816(c[2 * p + 1], a0, a1, a2, a3, b2, b3);
            }
        }
        if (t + 1 < NT) STORE_TILE((t + 1) & 1);
        __syncthreads();
    }

    // z row sums
#pragma unroll
    for (int r = 0; r < 8; r++) {
        float zz = z[r];
#pragma unroll
        for (int o = 16; o; o >>= 1) zz += __shfl_xor_sync(0xffffffffu, zz, o);
        if (lane == 0) s_z[wid * 8 + r] = zz;
    }
    __syncthreads();

    // epilogue
    const int mlo = mtile * 16 + (lane >> 2);          // local row (lo)
    const float zlo = s_z[mlo], zhi = s_z[mlo + 8];
    const float invlo = zlo > 0.f ? 1.f / zlo : 0.f;
    const float invhi = zhi > 0.f ? 1.f / zhi : 0.f;
    float* olo = out + (rbase + row0 + mlo) * OUT_DIM + nh * 64 + 2 * (lane & 3);
    float* ohi = olo + 8 * OUT_DIM;
#pragma unroll
    for (int q = 0; q < 8; q++) {
        *(float2*)(olo + q * 8) = make_float2(c[q][0] * invlo, c[q][1] * invlo);
        *(float2*)(ohi + q * 8) = make_float2(c[q][2] * invhi, c[q][3] * invhi);
    }
}

// ---------------------------------------------------------------------------
extern "C" void kernel_launch(void* const* d_in, const int* in_sizes, int n_in,
                              void* d_out, int out_size) {
    const float* x     = (const float*)d_in[0];   // [4,4096,256]
    const float* A     = (const float*)d_in[1];   // [4,4096,4096]
    const float* W     = (const float*)d_in[2];   // [256,128]
    const float* a_src = (const float*)d_in[3];   // [128]
    const float* a_dst = (const float*)d_in[4];   // [128]
    float* out = (float*)d_out;                   // [4,4096,128]

    cudaFuncSetAttribute(kAB, cudaFuncAttributeMaxDynamicSharedMemorySize,
                         DSM_BYTES);

    k1_gemm<<<NROWS / 64, 256>>>(x, W);
    k2_sd  <<<NROWS / 8,  256>>>(a_src, a_dst);
    kAB    <<<NROWS / RCTA, 256, DSM_BYTES>>>(A, out);
    (void)in_sizes; (void)n_in; (void)out_size;
}